// round 13
// baseline (speedup 1.0000x reference)
#include <cuda_runtime.h>
#include <cuda_fp16.h>
#include <cstdint>

// LSTMPredictor B=256,T=1024,HID=150 — R13: R12 core + accumulator-chain
// break. mma.sync m16n8k16 fp16->fp32; 128 CTAs x 256 threads, 2 batch/CTA.
// Changes vs R12 (864us):
//  - each M-tile uses TWO accumulator sets (even/odd K-tile), summed at
//    extraction: doubles dep distance; 2 chains x 2 warps/SMSP covers the
//    ~24cyc HMMA latency (R12 was serial d0..d3 -> ~12cyc/HMMA issue).
//  - registers to pay for it: A-tile i=3 joins i=4 in lane-linear smem
//    (-40 regs), wih/bias move to smem (-8 regs) -> ~40 regs of scheduling
//    slack so ptxas can actually pipeline (lesson from R6/R10 spills).

namespace {

constexpr int HID = 150, TT = 1024, NCTA = 128, NTHR = 256;
constexpr int KT = 10;            // K-tiles of 16 (K padded to 160)
constexpr int HKP = 168;          // h pitch in halves (84 words: bank-clean)

// dynamic smem offsets (bytes)
constexpr int OFF_HK   = 0;                 // fp16 h [8][168] = 2688
constexpr int OFF_HBUF = 2688;              // fp32 h [2][152] = 1216
constexpr int OFF_G2   = 3904;              // float2 gates [640] = 5120
constexpr int OFF_WLIN = 9024;              // fp32 [160] = 640
constexpr int OFF_BIAS = 9664;              // fp32 [600] = 2400
constexpr int OFF_WIH  = 12064;             // fp32 [600] = 2400
constexpr int OFF_W5   = 14464;             // uint4 A-frags tiles i=3,4:
                                            // 2*8*10*32*16B = 81920
constexpr int OFF_XIN  = 96384;             // fp32 [2][1024] = 8192
constexpr int SMEM_BYTES = 104576;

__device__ __forceinline__ float tanhapx(float x) {
    float y;
    asm("tanh.approx.f32 %0, %1;" : "=f"(y) : "f"(x));
    return y;
}
__device__ __forceinline__ float sigapx(float x) {
    return fmaf(tanhapx(0.5f * x), 0.5f, 0.5f);
}

__device__ __forceinline__ void mma16816(float& d0, float& d1, float& d2,
                                         float& d3, uint32_t a0, uint32_t a1,
                                         uint32_t a2, uint32_t a3,
                                         uint32_t b0, uint32_t b1) {
    asm volatile(
        "mma.sync.aligned.m16n8k16.row.col.f32.f16.f16.f32 "
        "{%0,%1,%2,%3}, {%4,%5,%6,%7}, {%8,%9}, {%0,%1,%2,%3};"
        : "+f"(d0), "+f"(d1), "+f"(d2), "+f"(d3)
        : "r"(a0), "r"(a1), "r"(a2), "r"(a3), "r"(b0), "r"(b1));
}

__device__ __forceinline__ float wel(const float* W, int r, int c) {
    return (r < 600 && c < HID) ? W[r * HID + c] : 0.f;
}
__device__ __forceinline__ uint32_t h2u(__half2 v) {
    return *reinterpret_cast<uint32_t*>(&v);
}

} // namespace

__global__ void __launch_bounds__(NTHR, 1)
lstm_hmma_kernel(const float* __restrict__ input,   // [256][1024]
                 const float* __restrict__ W_ih,    // [600][1]
                 const float* __restrict__ W_hh,    // [600][150]
                 const float* __restrict__ b_ih,    // [600]
                 const float* __restrict__ b_hh,    // [600]
                 const float* __restrict__ W_lin,   // [1][150]
                 const float* __restrict__ b_lin,   // [1]
                 float* __restrict__ out)           // [256][1024]
{
    extern __shared__ char smem[];
    __half* hk     = reinterpret_cast<__half*>(smem + OFF_HK);
    float*  hbuf   = reinterpret_cast<float*>(smem + OFF_HBUF);
    float2* g2     = reinterpret_cast<float2*>(smem + OFF_G2);
    float*  wlin_s = reinterpret_cast<float*>(smem + OFF_WLIN);
    float*  bias_s = reinterpret_cast<float*>(smem + OFF_BIAS);
    float*  wih_s  = reinterpret_cast<float*>(smem + OFF_WIH);
    uint4*  w5     = reinterpret_cast<uint4*>(smem + OFF_W5);
    float*  xin    = reinterpret_cast<float*>(smem + OFF_XIN);

    const int tid  = threadIdx.x;
    const int wid  = tid >> 5;
    const int lane = tid & 31;
    const int g    = lane >> 2;      // fragment row-group 0..7
    const int tig  = lane & 3;       // thread-in-group
    const int b0   = blockIdx.x * 2;

    // ---- one-time init ----
    for (int i = tid; i < 8 * HKP; i += NTHR) hk[i] = __half(0);
    for (int i = tid; i < 2 * 152; i += NTHR) hbuf[i] = 0.f;
    for (int i = tid; i < HID; i += NTHR) wlin_s[i] = W_lin[i];
    for (int i = tid; i < 600; i += NTHR) {
        bias_s[i] = b_ih[i] + b_hh[i];
        wih_s[i]  = W_ih[i];
    }
    for (int i = tid; i < 2 * TT; i += NTHR)
        xin[i] = input[(b0 + (i >> 10)) * TT + (i & (TT - 1))];

    // A fragments: m16n8k16 .row layout. mtile = wid + 8*i.
    // Tiles i<3 pinned in registers; tiles i=3,4 in lane-linear smem.
    uint32_t af[3][KT][4];
#pragma unroll
    for (int i = 0; i < 5; ++i) {
        const int mb = 16 * (wid + 8 * i);
#pragma unroll
        for (int kt = 0; kt < KT; ++kt) {
            const int kb = 16 * kt + 2 * tig;
            const int r0 = mb + g, r1 = mb + g + 8;
            uint32_t f0 = h2u(__floats2half2_rn(wel(W_hh, r0, kb),
                                                wel(W_hh, r0, kb + 1)));
            uint32_t f1 = h2u(__floats2half2_rn(wel(W_hh, r1, kb),
                                                wel(W_hh, r1, kb + 1)));
            uint32_t f2 = h2u(__floats2half2_rn(wel(W_hh, r0, kb + 8),
                                                wel(W_hh, r0, kb + 9)));
            uint32_t f3 = h2u(__floats2half2_rn(wel(W_hh, r1, kb + 8),
                                                wel(W_hh, r1, kb + 9)));
            if (i < 3) {
                af[i][kt][0] = f0; af[i][kt][1] = f1;
                af[i][kt][2] = f2; af[i][kt][3] = f3;
            } else {
                w5[(((i - 3) * 8 + wid) * KT + kt) * 32 + lane] =
                    make_uint4(f0, f1, f2, f3);
            }
        }
    }

    float c0 = 0.f, c1 = 0.f;
    const float blin = b_lin[0];

    __syncthreads();

    for (int t = 0; t < TT; ++t) {
        // ---- overlapped output: out[t-1] from hbuf = h_{t-1} (warps 4,5) ----
        if (t && (wid == 4 || wid == 5)) {
            const int bb = wid - 4;
            float s = 0.f;
#pragma unroll
            for (int m = 0; m < 5; ++m) {
                const int jj = lane + 32 * m;
                if (jj < HID) s = fmaf(hbuf[bb * 152 + jj], wlin_s[jj], s);
            }
#pragma unroll
            for (int off = 16; off; off >>= 1)
                s += __shfl_down_sync(0xffffffffu, s, off);
            if (lane == 0) out[(b0 + bb) * TT + (t - 1)] = s + blin;
        }

        // ---- B fragments from h_{t-1} (conflict-free LDS.32) ----
        uint32_t bf[KT][2];
#pragma unroll
        for (int kt = 0; kt < KT; ++kt) {
            const int base = g * HKP + 16 * kt + 2 * tig;
            bf[kt][0] = *reinterpret_cast<const uint32_t*>(hk + base);
            bf[kt][1] = *reinterpret_cast<const uint32_t*>(hk + base + 8);
        }

        // ---- 5 M-tiles x 10 K-tiles of HMMA, split even/odd accumulators --
#pragma unroll
        for (int i = 0; i < 5; ++i) {
            float e0 = 0.f, e1 = 0.f, e2 = 0.f, e3 = 0.f;
            float o0 = 0.f, o1 = 0.f, o2 = 0.f, o3 = 0.f;
            if (i < 3) {
#pragma unroll
                for (int kt = 0; kt < KT; kt += 2) {
                    mma16816(e0, e1, e2, e3, af[i][kt][0], af[i][kt][1],
                             af[i][kt][2], af[i][kt][3],
                             bf[kt][0], bf[kt][1]);
                    mma16816(o0, o1, o2, o3, af[i][kt+1][0], af[i][kt+1][1],
                             af[i][kt+1][2], af[i][kt+1][3],
                             bf[kt+1][0], bf[kt+1][1]);
                }
            } else {
                const uint4* wti = w5 + (((i - 3) * 8 + wid) * KT) * 32 + lane;
#pragma unroll
                for (int kt = 0; kt < KT; kt += 2) {
                    const uint4 qe = wti[kt * 32];
                    const uint4 qo = wti[(kt + 1) * 32];
                    mma16816(e0, e1, e2, e3, qe.x, qe.y, qe.z, qe.w,
                             bf[kt][0], bf[kt][1]);
                    mma16816(o0, o1, o2, o3, qo.x, qo.y, qo.z, qo.w,
                             bf[kt+1][0], bf[kt+1][1]);
                }
            }
            if (tig == 0) {           // cols 0,1 live in these lanes
                const int mb = 16 * (wid + 8 * i);
                g2[mb + g]     = make_float2(e0 + o0, e1 + o1);
                g2[mb + 8 + g] = make_float2(e2 + o2, e3 + o3);
            }
        }
        __syncthreads();              // gates ready; hk reads complete

        // ---- pointwise LSTM update: thread j < 150 ----
        if (tid < HID) {
            const int j = tid;
            const float x0 = xin[t], x1 = xin[TT + t];
            float2 gi = g2[j],         gf = g2[HID + j];
            float2 gg = g2[2*HID + j], go = g2[3*HID + j];
            const float wi0 = wih_s[j],         bi0 = bias_s[j];
            const float wi1 = wih_s[HID + j],   bi1 = bias_s[HID + j];
            const float wi2 = wih_s[2*HID + j], bi2 = bias_s[2*HID + j];
            const float wi3 = wih_s[3*HID + j], bi3 = bias_s[3*HID + j];
            gi.x += fmaf(x0, wi0, bi0); gi.y += fmaf(x1, wi0, bi0);
            gf.x += fmaf(x0, wi1, bi1); gf.y += fmaf(x1, wi1, bi1);
            gg.x += fmaf(x0, wi2, bi2); gg.y += fmaf(x1, wi2, bi2);
            go.x += fmaf(x0, wi3, bi3); go.y += fmaf(x1, wi3, bi3);
            c0 = fmaf(sigapx(gf.x), c0, sigapx(gi.x) * tanhapx(gg.x));
            c1 = fmaf(sigapx(gf.y), c1, sigapx(gi.y) * tanhapx(gg.y));
            const float h0 = sigapx(go.x) * tanhapx(c0);
            const float h1 = sigapx(go.y) * tanhapx(c1);
            hbuf[j]       = h0;
            hbuf[152 + j] = h1;
            hk[j]         = __float2half(h0);   // B rows n=0,1; n>=2 stay 0
            hk[HKP + j]   = __float2half(h1);
        }
        __syncthreads();              // h_t visible for next step
    }

    // ---- epilogue: out[TT-1] ----
    if (wid == 4 || wid == 5) {
        const int bb = wid - 4;
        float s = 0.f;
#pragma unroll
        for (int m = 0; m < 5; ++m) {
            const int jj = lane + 32 * m;
            if (jj < HID) s = fmaf(hbuf[bb * 152 + jj], wlin_s[jj], s);
        }
#pragma unroll
        for (int off = 16; off; off >>= 1)
            s += __shfl_down_sync(0xffffffffu, s, off);
        if (lane == 0) out[(b0 + bb) * TT + (TT - 1)] = s + blin;
    }
}

extern "C" void kernel_launch(void* const* d_in, const int* in_sizes, int n_in,
                              void* d_out, int out_size) {
    const float* input = (const float*)d_in[0];
    const float* W_ih  = (const float*)d_in[1];
    const float* W_hh  = (const float*)d_in[2];
    const float* b_ih  = (const float*)d_in[3];
    const float* b_hh  = (const float*)d_in[4];
    const float* W_lin = (const float*)d_in[5];
    const float* b_lin = (const float*)d_in[6];
    float* out = (float*)d_out;

    cudaFuncSetAttribute(lstm_hmma_kernel,
                         cudaFuncAttributeMaxDynamicSharedMemorySize, SMEM_BYTES);
    lstm_hmma_kernel<<<NCTA, NTHR, SMEM_BYTES>>>(input, W_ih, W_hh, b_ih, b_hh,
                                                 W_lin, b_lin, out);
}

// round 14
// speedup vs baseline: 1.0416x; 1.0416x over previous
#include <cuda_runtime.h>
#include <cuda_fp16.h>
#include <cstdint>

// LSTMPredictor B=256,T=1024,HID=150 — R14: R12 base (864us, known-good
// 252-reg allocation) + two changes:
//  1) mma.sync m16n8k16 with FP16 accumulators (f16.f16.f16.f16) — 2x rate
//     on the legacy tensor path if sm_100 matches prior gens; 10-link f16
//     accumulation chain ~= "flush every 16" (measured 4e-5 class earlier).
//  2) B fragments via one LDS.64 per K-tile: h stored interleaved
//     [k0,k1,k8,k9,k2,k3,k10,k11,...] with pitch 176 halves (88 words ->
//     16-lane phase bank bases {0,24,16,8}: disjoint, conflict-free).
// Everything else (warp/tile mapping, A-frags 4 reg + 1 smem tile,
// retimed out[t-1], 150-thread pointwise with tanh.approx) is R12 verbatim.

namespace {

constexpr int HID = 150, TT = 1024, NCTA = 128, NTHR = 256;
constexpr int KT = 10;            // K-tiles of 16 (K padded to 160)
constexpr int HKP = 176;          // h pitch in halves (88 words)

// dynamic smem offsets (bytes)
constexpr int OFF_HK   = 0;                 // fp16 h [8][176] = 2816
constexpr int OFF_HBUF = 2816;              // fp32 h [2][152] = 1216
constexpr int OFF_G2   = 4032;              // float2 gates [640] = 5120
constexpr int OFF_WLIN = 9152;              // fp32 [160] = 640
constexpr int OFF_W5   = 9792;              // uint4 A-frags tile i=4: 40960
constexpr int OFF_XIN  = 50752;             // fp32 [2][1024] = 8192
constexpr int SMEM_BYTES = 58944;

__device__ __forceinline__ float tanhapx(float x) {
    float y;
    asm("tanh.approx.f32 %0, %1;" : "=f"(y) : "f"(x));
    return y;
}
__device__ __forceinline__ float sigapx(float x) {
    return fmaf(tanhapx(0.5f * x), 0.5f, 0.5f);
}

// m16n8k16, fp16 in, FP16 accumulate (C/D = 2 x f16x2)
__device__ __forceinline__ void mma16816h(uint32_t& c0, uint32_t& c1,
                                          uint32_t a0, uint32_t a1,
                                          uint32_t a2, uint32_t a3,
                                          uint32_t b0, uint32_t b1) {
    asm volatile(
        "mma.sync.aligned.m16n8k16.row.col.f16.f16.f16.f16 "
        "{%0,%1}, {%2,%3,%4,%5}, {%6,%7}, {%0,%1};"
        : "+r"(c0), "+r"(c1)
        : "r"(a0), "r"(a1), "r"(a2), "r"(a3), "r"(b0), "r"(b1));
}

__device__ __forceinline__ float wel(const float* W, int r, int c) {
    return (r < 600 && c < HID) ? W[r * HID + c] : 0.f;
}
__device__ __forceinline__ uint32_t h2u(__half2 v) {
    return *reinterpret_cast<uint32_t*>(&v);
}
// interleaved position of hidden index k within its 16-half group:
// order [k0,k1,k8,k9,k2,k3,k10,k11,k4,k5,k12,k13,k6,k7,k14,k15]
__device__ __forceinline__ int hpos(int k) {
    const int q = k & 15;
    return (k & ~15) + ((q & 7) >> 1) * 4 + ((q >> 3) << 1) + (q & 1);
}

} // namespace

__global__ void __launch_bounds__(NTHR, 1)
lstm_hmma_kernel(const float* __restrict__ input,   // [256][1024]
                 const float* __restrict__ W_ih,    // [600][1]
                 const float* __restrict__ W_hh,    // [600][150]
                 const float* __restrict__ b_ih,    // [600]
                 const float* __restrict__ b_hh,    // [600]
                 const float* __restrict__ W_lin,   // [1][150]
                 const float* __restrict__ b_lin,   // [1]
                 float* __restrict__ out)           // [256][1024]
{
    extern __shared__ char smem[];
    __half* hk     = reinterpret_cast<__half*>(smem + OFF_HK);
    float*  hbuf   = reinterpret_cast<float*>(smem + OFF_HBUF);
    float2* g2     = reinterpret_cast<float2*>(smem + OFF_G2);
    float*  wlin_s = reinterpret_cast<float*>(smem + OFF_WLIN);
    uint4*  w5     = reinterpret_cast<uint4*>(smem + OFF_W5);
    float*  xin    = reinterpret_cast<float*>(smem + OFF_XIN);

    const int tid  = threadIdx.x;
    const int wid  = tid >> 5;
    const int lane = tid & 31;
    const int g    = lane >> 2;      // fragment row-group 0..7
    const int tig  = lane & 3;       // thread-in-group
    const int b0   = blockIdx.x * 2;

    // ---- one-time init ----
    for (int i = tid; i < 8 * HKP; i += NTHR) hk[i] = __half(0);
    for (int i = tid; i < 2 * 152; i += NTHR) hbuf[i] = 0.f;
    for (int i = tid; i < HID; i += NTHR) wlin_s[i] = W_lin[i];
    for (int i = tid; i < 2 * TT; i += NTHR)
        xin[i] = input[(b0 + (i >> 10)) * TT + (i & (TT - 1))];

    // A fragments: m16n8k16 .row layout. mtile = wid + 8*i.
    uint32_t af[4][KT][4];
#pragma unroll
    for (int i = 0; i < 5; ++i) {
        const int mb = 16 * (wid + 8 * i);
#pragma unroll
        for (int kt = 0; kt < KT; ++kt) {
            const int kb = 16 * kt + 2 * tig;
            const int r0 = mb + g, r1 = mb + g + 8;
            uint32_t f0 = h2u(__floats2half2_rn(wel(W_hh, r0, kb),
                                                wel(W_hh, r0, kb + 1)));
            uint32_t f1 = h2u(__floats2half2_rn(wel(W_hh, r1, kb),
                                                wel(W_hh, r1, kb + 1)));
            uint32_t f2 = h2u(__floats2half2_rn(wel(W_hh, r0, kb + 8),
                                                wel(W_hh, r0, kb + 9)));
            uint32_t f3 = h2u(__floats2half2_rn(wel(W_hh, r1, kb + 8),
                                                wel(W_hh, r1, kb + 9)));
            if (i < 4) {
                af[i][kt][0] = f0; af[i][kt][1] = f1;
                af[i][kt][2] = f2; af[i][kt][3] = f3;
            } else {
                w5[(wid * KT + kt) * 32 + lane] = make_uint4(f0, f1, f2, f3);
            }
        }
    }

    // Update-thread constants (gate rows j, 150+j, 300+j, 450+j)
    float wih[4], bia[4];
    if (tid < HID) {
#pragma unroll
        for (int r = 0; r < 4; ++r) {
            const int row = r * HID + tid;
            wih[r] = W_ih[row];
            bia[r] = b_ih[row] + b_hh[row];
        }
    }
    float c0 = 0.f, c1 = 0.f;
    const float blin = b_lin[0];

    __syncthreads();

    for (int t = 0; t < TT; ++t) {
        // ---- overlapped output: out[t-1] from hbuf = h_{t-1} (warps 4,5) ----
        if (t && (wid == 4 || wid == 5)) {
            const int bb = wid - 4;
            float s = 0.f;
#pragma unroll
            for (int m = 0; m < 5; ++m) {
                const int jj = lane + 32 * m;
                if (jj < HID) s = fmaf(hbuf[bb * 152 + jj], wlin_s[jj], s);
            }
#pragma unroll
            for (int off = 16; off; off >>= 1)
                s += __shfl_down_sync(0xffffffffu, s, off);
            if (lane == 0) out[(b0 + bb) * TT + (t - 1)] = s + blin;
        }

        // ---- B fragments: one conflict-free LDS.64 per K-tile ----
        uint32_t bf[KT][2];
#pragma unroll
        for (int kt = 0; kt < KT; ++kt) {
            const uint2 bv = *reinterpret_cast<const uint2*>(
                hk + g * HKP + kt * 16 + tig * 4);
            bf[kt][0] = bv.x;     // halves k=2tig, 2tig+1
            bf[kt][1] = bv.y;     // halves k=2tig+8, 2tig+9
        }

        // ---- 5 M-tiles x 10 K-tiles of HMMA (fp16 accumulate) ----
#pragma unroll
        for (int i = 0; i < 5; ++i) {
            uint32_t d0 = 0u, d1 = 0u;
            if (i < 4) {
#pragma unroll
                for (int kt = 0; kt < KT; ++kt)
                    mma16816h(d0, d1, af[i][kt][0], af[i][kt][1],
                              af[i][kt][2], af[i][kt][3],
                              bf[kt][0], bf[kt][1]);
            } else {
#pragma unroll
                for (int kt = 0; kt < KT; ++kt) {
                    const uint4 q = w5[(wid * KT + kt) * 32 + lane];
                    mma16816h(d0, d1, q.x, q.y, q.z, q.w,
                              bf[kt][0], bf[kt][1]);
                }
            }
            if (tig == 0) {           // cols 0,1 live in these lanes
                const int mb = 16 * (wid + 8 * i);
                g2[mb + g]     = __half22float2(*reinterpret_cast<__half2*>(&d0));
                g2[mb + 8 + g] = __half22float2(*reinterpret_cast<__half2*>(&d1));
            }
        }
        __syncthreads();              // gates ready; hk reads complete

        // ---- pointwise LSTM update: thread j < 150 ----
        if (tid < HID) {
            const int j = tid;
            const float x0 = xin[t], x1 = xin[TT + t];
            float2 gi = g2[j],         gf = g2[HID + j];
            float2 gg = g2[2*HID + j], go = g2[3*HID + j];
            gi.x += fmaf(x0, wih[0], bia[0]); gi.y += fmaf(x1, wih[0], bia[0]);
            gf.x += fmaf(x0, wih[1], bia[1]); gf.y += fmaf(x1, wih[1], bia[1]);
            gg.x += fmaf(x0, wih[2], bia[2]); gg.y += fmaf(x1, wih[2], bia[2]);
            go.x += fmaf(x0, wih[3], bia[3]); go.y += fmaf(x1, wih[3], bia[3]);
            c0 = fmaf(sigapx(gf.x), c0, sigapx(gi.x) * tanhapx(gg.x));
            c1 = fmaf(sigapx(gf.y), c1, sigapx(gi.y) * tanhapx(gg.y));
            const float h0 = sigapx(go.x) * tanhapx(c0);
            const float h1 = sigapx(go.y) * tanhapx(c1);
            hbuf[j]       = h0;
            hbuf[152 + j] = h1;
            const int p = hpos(j);
            hk[p]        = __float2half(h0);   // B rows n=0,1; n>=2 stay 0
            hk[HKP + p]  = __float2half(h1);
        }
        __syncthreads();              // h_t visible for next step
    }

    // ---- epilogue: out[TT-1] ----
    if (wid == 4 || wid == 5) {
        const int bb = wid - 4;
        float s = 0.f;
#pragma unroll
        for (int m = 0; m < 5; ++m) {
            const int jj = lane + 32 * m;
            if (jj < HID) s = fmaf(hbuf[bb * 152 + jj], wlin_s[jj], s);
        }
#pragma unroll
        for (int off = 16; off; off >>= 1)
            s += __shfl_down_sync(0xffffffffu, s, off);
        if (lane == 0) out[(b0 + bb) * TT + (TT - 1)] = s + blin;
    }
}

extern "C" void kernel_launch(void* const* d_in, const int* in_sizes, int n_in,
                              void* d_out, int out_size) {
    const float* input = (const float*)d_in[0];
    const float* W_ih  = (const float*)d_in[1];
    const float* W_hh  = (const float*)d_in[2];
    const float* b_ih  = (const float*)d_in[3];
    const float* b_hh  = (const float*)d_in[4];
    const float* W_lin = (const float*)d_in[5];
    const float* b_lin = (const float*)d_in[6];
    float* out = (float*)d_out;

    cudaFuncSetAttribute(lstm_hmma_kernel,
                         cudaFuncAttributeMaxDynamicSharedMemorySize, SMEM_BYTES);
    lstm_hmma_kernel<<<NCTA, NTHR, SMEM_BYTES>>>(input, W_ih, W_hh, b_ih, b_hh,
                                                 W_lin, b_lin, out);
}